// round 2
// baseline (speedup 1.0000x reference)
#include <cuda_runtime.h>
#include <math.h>

// Problem constants
#define BATCH 2
#define SEQ   2048
#define DMODEL 1024
#define NHEAD 16
#define HDIM  64
#define D3    3072          // 3*DMODEL
#define MROWS (BATCH*SEQ)   // 4096

// Scratch (no cudaMalloc allowed)
__device__ float g_qkv[(size_t)MROWS * D3];     // [B*S, 3*D]
__device__ float g_attn[(size_t)MROWS * DMODEL]; // [B*S, D]

// ---------------------------------------------------------------------------
// SGEMM NT + bias:  C[M,N] = A[M,K] * B[N,K]^T + bias[N]
// 128x128 tile, BK=8, 256 threads, 8x8 per thread (split 4+4).
// M,N,K all multiples of 128/8 for our shapes -> no bounds checks.
// ---------------------------------------------------------------------------
__global__ __launch_bounds__(256)
void sgemm_nt_bias(const float* __restrict__ A, const float* __restrict__ Bm,
                   const float* __restrict__ bias, float* __restrict__ C,
                   int M, int N, int K)
{
    __shared__ __align__(16) float As[8 * 128];
    __shared__ __align__(16) float Bs[8 * 128];

    const int tid = threadIdx.x;
    const int tr = tid >> 4;          // 0..15 (row group)
    const int tc = tid & 15;          // 0..15 (col group)
    const int row0 = blockIdx.y * 128;
    const int col0 = blockIdx.x * 128;

    const float* Ablk = A + (size_t)row0 * K;
    const float* Bblk = Bm + (size_t)col0 * K;

    const int lrow = tid >> 1;        // 0..127
    const int lk   = (tid & 1) * 4;   // 0 or 4

    float acc[8][8];
#pragma unroll
    for (int i = 0; i < 8; i++)
#pragma unroll
        for (int j = 0; j < 8; j++) acc[i][j] = 0.f;

    for (int k0 = 0; k0 < K; k0 += 8) {
        float4 av = *(const float4*)(Ablk + (size_t)lrow * K + k0 + lk);
        float4 bv = *(const float4*)(Bblk + (size_t)lrow * K + k0 + lk);
        __syncthreads();   // previous iteration's reads complete
        As[(lk + 0) * 128 + lrow] = av.x;
        As[(lk + 1) * 128 + lrow] = av.y;
        As[(lk + 2) * 128 + lrow] = av.z;
        As[(lk + 3) * 128 + lrow] = av.w;
        Bs[(lk + 0) * 128 + lrow] = bv.x;
        Bs[(lk + 1) * 128 + lrow] = bv.y;
        Bs[(lk + 2) * 128 + lrow] = bv.z;
        Bs[(lk + 3) * 128 + lrow] = bv.w;
        __syncthreads();

#pragma unroll
        for (int kk = 0; kk < 8; kk++) {
            float4 a0 = *(const float4*)(As + kk * 128 + tr * 4);
            float4 a1 = *(const float4*)(As + kk * 128 + 64 + tr * 4);
            float4 b0 = *(const float4*)(Bs + kk * 128 + tc * 4);
            float4 b1 = *(const float4*)(Bs + kk * 128 + 64 + tc * 4);
            float a[8] = {a0.x, a0.y, a0.z, a0.w, a1.x, a1.y, a1.z, a1.w};
            float b[8] = {b0.x, b0.y, b0.z, b0.w, b1.x, b1.y, b1.z, b1.w};
#pragma unroll
            for (int i = 0; i < 8; i++)
#pragma unroll
                for (int j = 0; j < 8; j++)
                    acc[i][j] = fmaf(a[i], b[j], acc[i][j]);
        }
    }

#pragma unroll
    for (int i = 0; i < 8; i++) {
        int r = row0 + ((i < 4) ? (tr * 4 + i) : (64 + tr * 4 + i - 4));
#pragma unroll
        for (int jh = 0; jh < 2; jh++) {
            int c = col0 + jh * 64 + tc * 4;
            float4 bb = *(const float4*)(bias + c);
            float4 o;
            o.x = acc[i][jh * 4 + 0] + bb.x;
            o.y = acc[i][jh * 4 + 1] + bb.y;
            o.z = acc[i][jh * 4 + 2] + bb.z;
            o.w = acc[i][jh * 4 + 3] + bb.w;
            *(float4*)(C + (size_t)r * N + c) = o;
        }
    }
}

// ---------------------------------------------------------------------------
// Fused flash attention, fp32, hd=64.
// Block: 256 threads (16x16), 64 query rows per block, K/V tiles of 64.
// Each thread owns a 4x4 patch of the 64x64 score tile and a 4x4 patch of
// the 64-wide output.  Row reductions via 16-lane shfl.
// qkv layout per row (b*S+s): [3, H, 64]; Q at h*64, K at 1024+h*64, V at 2048+h*64
// ---------------------------------------------------------------------------
#define SMQ_STRIDE 65
#define SMK_STRIDE 68
// smem floats: Qs 64*65, Ps 64*65, Kt 64*68, Vs 64*68
#define ATTN_SMEM_FLOATS (64*SMQ_STRIDE*2 + 64*SMK_STRIDE*2)

__global__ __launch_bounds__(256)
void flash_attn_fp32(const float* __restrict__ qkv, float* __restrict__ attn)
{
    extern __shared__ __align__(16) float sm[];
    float* Qs = sm;                         // [64][65]  natural
    float* Ps = Qs + 64 * SMQ_STRIDE;       // [64][65]  natural
    float* Kt = Ps + 64 * SMQ_STRIDE;       // [64][68]  transposed: Kt[d][s]
    float* Vs = Kt + 64 * SMK_STRIDE;       // [64][68]  natural: Vs[s][d]

    const int tid = threadIdx.x;
    const int tx = tid & 15;                // score-col group
    const int ty = tid >> 4;                // score-row group
    const int bh = blockIdx.y;
    const int b = bh >> 4;
    const int h = bh & 15;
    const int q0 = blockIdx.x * 64;

    const float scale = 0.125f;             // 1/sqrt(64)
    const float* base = qkv + (size_t)b * SEQ * D3;

    // Load + scale Q tile: rows q0..q0+63, 64 cols, natural layout
#pragma unroll
    for (int i = 0; i < 4; i++) {
        int idx = tid + i * 256;
        int s = idx >> 4;
        int d = (idx & 15) * 4;
        float4 q = *(const float4*)(base + (size_t)(q0 + s) * D3 + h * HDIM + d);
        Qs[s * SMQ_STRIDE + d + 0] = q.x * scale;
        Qs[s * SMQ_STRIDE + d + 1] = q.y * scale;
        Qs[s * SMQ_STRIDE + d + 2] = q.z * scale;
        Qs[s * SMQ_STRIDE + d + 3] = q.w * scale;
    }

    float m_i[4], l_i[4], o[4][4];
#pragma unroll
    for (int i = 0; i < 4; i++) {
        m_i[i] = -1e30f;
        l_i[i] = 0.f;
#pragma unroll
        for (int j = 0; j < 4; j++) o[i][j] = 0.f;
    }

    for (int kt = 0; kt < SEQ / 64; kt++) {
        const int k0 = kt * 64;
        // load K (transposed) and V tiles
#pragma unroll
        for (int i = 0; i < 4; i++) {
            int idx = tid + i * 256;
            int s = idx >> 4;
            int d = (idx & 15) * 4;
            const float* rp = base + (size_t)(k0 + s) * D3 + h * HDIM;
            float4 kv = *(const float4*)(rp + DMODEL + d);
            float4 vv = *(const float4*)(rp + 2 * DMODEL + d);
            Kt[(d + 0) * SMK_STRIDE + s] = kv.x;
            Kt[(d + 1) * SMK_STRIDE + s] = kv.y;
            Kt[(d + 2) * SMK_STRIDE + s] = kv.z;
            Kt[(d + 3) * SMK_STRIDE + s] = kv.w;
            *(float4*)(Vs + s * SMK_STRIDE + d) = vv;
        }
        __syncthreads();

        // S = Q * K^T  (4x4 per thread)
        float sc[4][4];
#pragma unroll
        for (int i = 0; i < 4; i++)
#pragma unroll
            for (int j = 0; j < 4; j++) sc[i][j] = 0.f;

#pragma unroll 16
        for (int kk = 0; kk < 64; kk++) {
            float4 kv = *(const float4*)(Kt + kk * SMK_STRIDE + tx * 4);
            float q0v = Qs[(ty * 4 + 0) * SMQ_STRIDE + kk];
            float q1v = Qs[(ty * 4 + 1) * SMQ_STRIDE + kk];
            float q2v = Qs[(ty * 4 + 2) * SMQ_STRIDE + kk];
            float q3v = Qs[(ty * 4 + 3) * SMQ_STRIDE + kk];
            sc[0][0] = fmaf(q0v, kv.x, sc[0][0]); sc[0][1] = fmaf(q0v, kv.y, sc[0][1]);
            sc[0][2] = fmaf(q0v, kv.z, sc[0][2]); sc[0][3] = fmaf(q0v, kv.w, sc[0][3]);
            sc[1][0] = fmaf(q1v, kv.x, sc[1][0]); sc[1][1] = fmaf(q1v, kv.y, sc[1][1]);
            sc[1][2] = fmaf(q1v, kv.z, sc[1][2]); sc[1][3] = fmaf(q1v, kv.w, sc[1][3]);
            sc[2][0] = fmaf(q2v, kv.x, sc[2][0]); sc[2][1] = fmaf(q2v, kv.y, sc[2][1]);
            sc[2][2] = fmaf(q2v, kv.z, sc[2][2]); sc[2][3] = fmaf(q2v, kv.w, sc[2][3]);
            sc[3][0] = fmaf(q3v, kv.x, sc[3][0]); sc[3][1] = fmaf(q3v, kv.y, sc[3][1]);
            sc[3][2] = fmaf(q3v, kv.z, sc[3][2]); sc[3][3] = fmaf(q3v, kv.w, sc[3][3]);
        }

        // online softmax per row (16 threads per row, shfl-xor within 16 lanes)
#pragma unroll
        for (int i = 0; i < 4; i++) {
            float rmax = fmaxf(fmaxf(sc[i][0], sc[i][1]), fmaxf(sc[i][2], sc[i][3]));
#pragma unroll
            for (int off = 8; off >= 1; off >>= 1)
                rmax = fmaxf(rmax, __shfl_xor_sync(0xffffffffu, rmax, off, 16));
            float mnew = fmaxf(m_i[i], rmax);
            float corr = __expf(m_i[i] - mnew);
            float rsum = 0.f;
#pragma unroll
            for (int j = 0; j < 4; j++) {
                float p = __expf(sc[i][j] - mnew);
                Ps[(ty * 4 + i) * SMQ_STRIDE + tx * 4 + j] = p;
                rsum += p;
            }
#pragma unroll
            for (int off = 8; off >= 1; off >>= 1)
                rsum += __shfl_xor_sync(0xffffffffu, rsum, off, 16);
            l_i[i] = l_i[i] * corr + rsum;
            m_i[i] = mnew;
#pragma unroll
            for (int j = 0; j < 4; j++) o[i][j] *= corr;
        }
        __syncthreads();

        // O += P * V
#pragma unroll 16
        for (int kk = 0; kk < 64; kk++) {
            float4 vv = *(const float4*)(Vs + kk * SMK_STRIDE + tx * 4);
            float p0 = Ps[(ty * 4 + 0) * SMQ_STRIDE + kk];
            float p1 = Ps[(ty * 4 + 1) * SMQ_STRIDE + kk];
            float p2 = Ps[(ty * 4 + 2) * SMQ_STRIDE + kk];
            float p3 = Ps[(ty * 4 + 3) * SMQ_STRIDE + kk];
            o[0][0] = fmaf(p0, vv.x, o[0][0]); o[0][1] = fmaf(p0, vv.y, o[0][1]);
            o[0][2] = fmaf(p0, vv.z, o[0][2]); o[0][3] = fmaf(p0, vv.w, o[0][3]);
            o[1][0] = fmaf(p1, vv.x, o[1][0]); o[1][1] = fmaf(p1, vv.y, o[1][1]);
            o[1][2] = fmaf(p1, vv.z, o[1][2]); o[1][3] = fmaf(p1, vv.w, o[1][3]);
            o[2][0] = fmaf(p2, vv.x, o[2][0]); o[2][1] = fmaf(p2, vv.y, o[2][1]);
            o[2][2] = fmaf(p2, vv.z, o[2][2]); o[2][3] = fmaf(p2, vv.w, o[2][3]);
            o[3][0] = fmaf(p3, vv.x, o[3][0]); o[3][1] = fmaf(p3, vv.y, o[3][1]);
            o[3][2] = fmaf(p3, vv.z, o[3][2]); o[3][3] = fmaf(p3, vv.w, o[3][3]);
        }
        __syncthreads();
    }

    // finalize and write attn[b, q0+row, h*64 + col]
#pragma unroll
    for (int i = 0; i < 4; i++) {
        float inv = 1.f / l_i[i];
        int row = q0 + ty * 4 + i;
        float4 ov;
        ov.x = o[i][0] * inv; ov.y = o[i][1] * inv;
        ov.z = o[i][2] * inv; ov.w = o[i][3] * inv;
        *(float4*)(attn + ((size_t)(b * SEQ + row)) * DMODEL + h * HDIM + tx * 4) = ov;
    }
}

// ---------------------------------------------------------------------------
extern "C" void kernel_launch(void* const* d_in, const int* in_sizes, int n_in,
                              void* d_out, int out_size)
{
    const float* x     = (const float*)d_in[0];
    const float* qkv_w = (const float*)d_in[1];
    const float* qkv_b = (const float*)d_in[2];
    const float* out_w = (const float*)d_in[3];
    const float* out_b = (const float*)d_in[4];
    float* out = (float*)d_out;

    float *qkv_buf, *attn_buf;
    cudaGetSymbolAddress((void**)&qkv_buf, g_qkv);
    cudaGetSymbolAddress((void**)&attn_buf, g_attn);

    const int smem_bytes = ATTN_SMEM_FLOATS * (int)sizeof(float);
    cudaFuncSetAttribute(flash_attn_fp32,
                         cudaFuncAttributeMaxDynamicSharedMemorySize, smem_bytes);

    // 1) QKV projection: [4096,1024] x [3072,1024]^T -> [4096,3072]
    {
        dim3 grid(D3 / 128, MROWS / 128);
        sgemm_nt_bias<<<grid, 256>>>(x, qkv_w, qkv_b, qkv_buf,
                                     MROWS, D3, DMODEL);
    }

    // 2) fused attention -> attn_buf [4096, 1024]
    {
        dim3 grid(SEQ / 64, BATCH * NHEAD);
        flash_attn_fp32<<<grid, 256, smem_bytes>>>(qkv_buf, attn_buf);
    }

    // 3) output projection: [4096,1024] x [1024,1024]^T -> [4096,1024]
    {
        dim3 grid(DMODEL / 128, MROWS / 128);
        sgemm_nt_bias<<<grid, 256>>>(attn_buf, out_w, out_b, out,
                                     MROWS, DMODEL, DMODEL);
    }
}

// round 3
// speedup vs baseline: 2.0441x; 2.0441x over previous
#include <cuda_runtime.h>
#include <math.h>

#define BATCH 2
#define SEQ   2048
#define DMODEL 1024
#define NHEAD 16
#define HDIM  64
#define D3    3072
#define MROWS (BATCH*SEQ)

__device__ float g_qkv[(size_t)MROWS * D3];
__device__ float g_attn[(size_t)MROWS * DMODEL];

__device__ __forceinline__ unsigned f2tf(float f) {
    unsigned u;
    asm("cvt.rna.tf32.f32 %0, %1;" : "=r"(u) : "f"(f));
    return u;
}

__device__ __forceinline__ void mma_tf32(float* d, const unsigned* a, const unsigned* b) {
    asm volatile(
        "mma.sync.aligned.m16n8k8.row.col.f32.tf32.tf32.f32 "
        "{%0,%1,%2,%3}, {%4,%5,%6,%7}, {%8,%9}, {%0,%1,%2,%3};\n"
        : "+f"(d[0]), "+f"(d[1]), "+f"(d[2]), "+f"(d[3])
        : "r"(a[0]), "r"(a[1]), "r"(a[2]), "r"(a[3]), "r"(b[0]), "r"(b[1]));
}

// ---------------------------------------------------------------------------
// Tensor-core GEMM NT + bias: C[M,N] = A[M,K]*B[N,K]^T + bias[N], tf32 mma.
// 128x128 tile, BK=32, 256 threads (8 warps, 4x2), warp tile 32x64.
// Smem layout permuted: element (row,k) at row*38 + (k%4)*8 + k/4.
// ---------------------------------------------------------------------------
#define GST 38

__global__ __launch_bounds__(256)
void gemm_tc(const float* __restrict__ A, const float* __restrict__ Bm,
             const float* __restrict__ bias, float* __restrict__ C,
             int M, int N, int K)
{
    __shared__ unsigned As[128 * GST];
    __shared__ unsigned Bs[128 * GST];

    const int tid  = threadIdx.x;
    const int warp = tid >> 5, lane = tid & 31;
    const int wm = warp >> 1, wn = warp & 1;
    const int g = lane >> 2, kq = lane & 3;
    const int row0 = blockIdx.y * 128, col0 = blockIdx.x * 128;

    const int lr  = tid >> 1;
    const int lkb = (tid & 1) * 16;
    const float* Ag = A  + (size_t)(row0 + lr) * K + lkb;
    const float* Bg = Bm + (size_t)(col0 + lr) * K + lkb;

    float4 pa[4], pb[4];
#pragma unroll
    for (int q = 0; q < 4; q++) {
        pa[q] = *(const float4*)(Ag + q * 4);
        pb[q] = *(const float4*)(Bg + q * 4);
    }

    float acc[2][8][4];
#pragma unroll
    for (int mt = 0; mt < 2; mt++)
#pragma unroll
        for (int nt = 0; nt < 8; nt++)
#pragma unroll
            for (int i = 0; i < 4; i++) acc[mt][nt][i] = 0.f;

    const int nk = K / 32;
    for (int kt = 0; kt < nk; kt++) {
        __syncthreads();
#pragma unroll
        for (int q = 0; q < 4; q++) {
            int j = (lkb >> 2) + q;
            unsigned* ap = As + lr * GST + j;
            ap[0]  = f2tf(pa[q].x); ap[8]  = f2tf(pa[q].y);
            ap[16] = f2tf(pa[q].z); ap[24] = f2tf(pa[q].w);
            unsigned* bp = Bs + lr * GST + j;
            bp[0]  = f2tf(pb[q].x); bp[8]  = f2tf(pb[q].y);
            bp[16] = f2tf(pb[q].z); bp[24] = f2tf(pb[q].w);
        }
        __syncthreads();

        if (kt + 1 < nk) {
            const float* Agn = Ag + (size_t)(kt + 1) * 32;
            const float* Bgn = Bg + (size_t)(kt + 1) * 32;
#pragma unroll
            for (int q = 0; q < 4; q++) {
                pa[q] = *(const float4*)(Agn + q * 4);
                pb[q] = *(const float4*)(Bgn + q * 4);
            }
        }

#pragma unroll
        for (int s = 0; s < 4; s++) {
            unsigned af[2][4];
#pragma unroll
            for (int mt = 0; mt < 2; mt++) {
                int r = wm * 32 + mt * 16 + g;
                const uint2 t0 = *(const uint2*)(As + r * GST + kq * 8 + 2 * s);
                const uint2 t1 = *(const uint2*)(As + (r + 8) * GST + kq * 8 + 2 * s);
                af[mt][0] = t0.x; af[mt][2] = t0.y;
                af[mt][1] = t1.x; af[mt][3] = t1.y;
            }
#pragma unroll
            for (int nt = 0; nt < 8; nt++) {
                int cI = wn * 64 + nt * 8 + g;
                const uint2 tb = *(const uint2*)(Bs + cI * GST + kq * 8 + 2 * s);
                unsigned bf[2] = {tb.x, tb.y};
                mma_tf32(acc[0][nt], af[0], bf);
                mma_tf32(acc[1][nt], af[1], bf);
            }
        }
    }

#pragma unroll
    for (int mt = 0; mt < 2; mt++) {
        int r = row0 + wm * 32 + mt * 16 + g;
#pragma unroll
        for (int nt = 0; nt < 8; nt++) {
            int c = col0 + wn * 64 + nt * 8 + 2 * kq;
            float2 bb = *(const float2*)(bias + c);
            float2 v0 = {acc[mt][nt][0] + bb.x, acc[mt][nt][1] + bb.y};
            float2 v1 = {acc[mt][nt][2] + bb.x, acc[mt][nt][3] + bb.y};
            *(float2*)(C + (size_t)r * N + c) = v0;
            *(float2*)(C + (size_t)(r + 8) * N + c) = v1;
        }
    }
}

// ---------------------------------------------------------------------------
// Flash attention with tf32 mma. 128 threads (4 warps), 64 q-rows per block.
// Warp w owns q rows [w*16, w*16+16). K/V tiles of 64 tokens, 32 tiles.
// Smem layouts (element (row,k) at row*80 + (k%4)*20 + k/4):
//   Qs[64 qrows][hd],  Ks[64 tokens][hd],  Ps[64 qrows][tokens],
//   Vt[64 d][tokens]  (transposed)
// ---------------------------------------------------------------------------
#define AST 80
#define ATTN_SMEM_BYTES (4 * 64 * AST * 4)

__global__ __launch_bounds__(128)
void attn_tc(const float* __restrict__ qkv, float* __restrict__ attn)
{
    extern __shared__ unsigned smu[];
    unsigned* Qs = smu;
    unsigned* Ks = Qs + 64 * AST;
    unsigned* Vt = Ks + 64 * AST;
    unsigned* Ps = Vt + 64 * AST;

    const int tid = threadIdx.x;
    const int warp = tid >> 5, lane = tid & 31;
    const int g = lane >> 2, kq = lane & 3;
    const int b = blockIdx.y >> 4, h = blockIdx.y & 15;
    const int q0 = blockIdx.x * 64;
    const float* base = qkv + (size_t)b * SEQ * D3;
    const float scale = 0.125f;

    // Load + scale Q into permuted smem
#pragma unroll
    for (int i = 0; i < 8; i++) {
        int e = i * 128 + tid;
        int row = e >> 4, idx = e & 15, d4 = idx * 4;
        float4 q = *(const float4*)(base + (size_t)(q0 + row) * D3 + h * HDIM + d4);
        unsigned* qp = Qs + row * AST + idx;
        qp[0]  = f2tf(q.x * scale); qp[20] = f2tf(q.y * scale);
        qp[40] = f2tf(q.z * scale); qp[60] = f2tf(q.w * scale);
    }
    __syncthreads();

    // Q fragments to registers (rows r0, r0+8)
    const int r0 = warp * 16 + g;
    unsigned qrow0[16], qrow1[16];
#pragma unroll
    for (int u = 0; u < 4; u++) {
        *(uint4*)&qrow0[u * 4] = *(const uint4*)(Qs + r0 * AST + kq * 20 + u * 4);
        *(uint4*)&qrow1[u * 4] = *(const uint4*)(Qs + (r0 + 8) * AST + kq * 20 + u * 4);
    }

    // Prefetch K/V tile 0
    float4 pk[8], pv[8];
    {
        const float* kb = base + DMODEL + h * HDIM;
        const float* vb = base + 2 * DMODEL + h * HDIM;
#pragma unroll
        for (int i = 0; i < 8; i++) {
            int e = i * 128 + tid;
            pk[i] = *(const float4*)(kb + (size_t)(e >> 4) * D3 + (e & 15) * 4);
        }
        int vs = tid >> 1;
#pragma unroll
        for (int q = 0; q < 8; q++) {
            int d4 = (tid & 1) * 4 + q * 8;
            pv[q] = *(const float4*)(vb + (size_t)vs * D3 + d4);
        }
    }

    float m0 = -1e30f, m1 = -1e30f, l0 = 0.f, l1 = 0.f;
    float o[8][4];
#pragma unroll
    for (int nt = 0; nt < 8; nt++)
#pragma unroll
        for (int i = 0; i < 4; i++) o[nt][i] = 0.f;

    for (int kt = 0; kt < SEQ / 64; kt++) {
        __syncthreads();
        // STS K (tokens, permuted hd)
#pragma unroll
        for (int i = 0; i < 8; i++) {
            int e = i * 128 + tid;
            int s = e >> 4, idx = e & 15;
            unsigned* kp = Ks + s * AST + idx;
            kp[0]  = f2tf(pk[i].x); kp[20] = f2tf(pk[i].y);
            kp[40] = f2tf(pk[i].z); kp[60] = f2tf(pk[i].w);
        }
        // STS V transposed (d rows, permuted tokens)
        {
            int s = tid >> 1;
            int pofs = (s & 3) * 20 + (s >> 2);
#pragma unroll
            for (int q = 0; q < 8; q++) {
                int d4 = (tid & 1) * 4 + q * 8;
                unsigned* vp = Vt + d4 * AST + pofs;
                vp[0]       = f2tf(pv[q].x);
                vp[AST]     = f2tf(pv[q].y);
                vp[2 * AST] = f2tf(pv[q].z);
                vp[3 * AST] = f2tf(pv[q].w);
            }
        }
        __syncthreads();

        if (kt + 1 < SEQ / 64) {
            int k0n = (kt + 1) * 64;
            const float* kb = base + (size_t)k0n * D3 + DMODEL + h * HDIM;
            const float* vb = base + (size_t)k0n * D3 + 2 * DMODEL + h * HDIM;
#pragma unroll
            for (int i = 0; i < 8; i++) {
                int e = i * 128 + tid;
                pk[i] = *(const float4*)(kb + (size_t)(e >> 4) * D3 + (e & 15) * 4);
            }
            int vs = tid >> 1;
#pragma unroll
            for (int q = 0; q < 8; q++) {
                int d4 = (tid & 1) * 4 + q * 8;
                pv[q] = *(const float4*)(vb + (size_t)vs * D3 + d4);
            }
        }

        // S = Q K^T
        float sfr[8][4];
#pragma unroll
        for (int nt = 0; nt < 8; nt++) {
#pragma unroll
            for (int i = 0; i < 4; i++) sfr[nt][i] = 0.f;
            unsigned kb[16];
            int col = nt * 8 + g;
#pragma unroll
            for (int u = 0; u < 4; u++)
                *(uint4*)&kb[u * 4] = *(const uint4*)(Ks + col * AST + kq * 20 + u * 4);
#pragma unroll
            for (int s = 0; s < 8; s++) {
                unsigned a[4] = {qrow0[2 * s], qrow1[2 * s], qrow0[2 * s + 1], qrow1[2 * s + 1]};
                unsigned bfr[2] = {kb[2 * s], kb[2 * s + 1]};
                mma_tf32(sfr[nt], a, bfr);
            }
        }

        // Online softmax (rows r0, r0+8); quad reduce over lanes sharing g
        float mx0 = -1e30f, mx1 = -1e30f;
#pragma unroll
        for (int nt = 0; nt < 8; nt++) {
            mx0 = fmaxf(mx0, fmaxf(sfr[nt][0], sfr[nt][1]));
            mx1 = fmaxf(mx1, fmaxf(sfr[nt][2], sfr[nt][3]));
        }
        mx0 = fmaxf(mx0, __shfl_xor_sync(0xffffffffu, mx0, 1));
        mx0 = fmaxf(mx0, __shfl_xor_sync(0xffffffffu, mx0, 2));
        mx1 = fmaxf(mx1, __shfl_xor_sync(0xffffffffu, mx1, 1));
        mx1 = fmaxf(mx1, __shfl_xor_sync(0xffffffffu, mx1, 2));
        float mn0 = fmaxf(m0, mx0), mn1 = fmaxf(m1, mx1);
        float corr0 = __expf(m0 - mn0), corr1 = __expf(m1 - mn1);

        float sum0 = 0.f, sum1 = 0.f;
#pragma unroll
        for (int nt = 0; nt < 8; nt++) {
            int c0 = nt * 8 + 2 * kq;
            float p0 = __expf(sfr[nt][0] - mn0);
            float p1 = __expf(sfr[nt][1] - mn0);
            float p2 = __expf(sfr[nt][2] - mn1);
            float p3 = __expf(sfr[nt][3] - mn1);
            sum0 += p0 + p1; sum1 += p2 + p3;
            Ps[r0 * AST + (c0 & 3) * 20 + (c0 >> 2)]                   = f2tf(p0);
            Ps[r0 * AST + ((c0 + 1) & 3) * 20 + ((c0 + 1) >> 2)]       = f2tf(p1);
            Ps[(r0 + 8) * AST + (c0 & 3) * 20 + (c0 >> 2)]             = f2tf(p2);
            Ps[(r0 + 8) * AST + ((c0 + 1) & 3) * 20 + ((c0 + 1) >> 2)] = f2tf(p3);
        }
        sum0 += __shfl_xor_sync(0xffffffffu, sum0, 1);
        sum0 += __shfl_xor_sync(0xffffffffu, sum0, 2);
        sum1 += __shfl_xor_sync(0xffffffffu, sum1, 1);
        sum1 += __shfl_xor_sync(0xffffffffu, sum1, 2);
        l0 = l0 * corr0 + sum0; m0 = mn0;
        l1 = l1 * corr1 + sum1; m1 = mn1;

#pragma unroll
        for (int nt = 0; nt < 8; nt++) {
            o[nt][0] *= corr0; o[nt][1] *= corr0;
            o[nt][2] *= corr1; o[nt][3] *= corr1;
        }
        __syncwarp();

        // P fragments
        unsigned prow0[16], prow1[16];
#pragma unroll
        for (int u = 0; u < 4; u++) {
            *(uint4*)&prow0[u * 4] = *(const uint4*)(Ps + r0 * AST + kq * 20 + u * 4);
            *(uint4*)&prow1[u * 4] = *(const uint4*)(Ps + (r0 + 8) * AST + kq * 20 + u * 4);
        }

        // O += P V
#pragma unroll
        for (int nt = 0; nt < 8; nt++) {
            unsigned vbf[16];
            int cd = nt * 8 + g;
#pragma unroll
            for (int u = 0; u < 4; u++)
                *(uint4*)&vbf[u * 4] = *(const uint4*)(Vt + cd * AST + kq * 20 + u * 4);
#pragma unroll
            for (int s = 0; s < 8; s++) {
                unsigned a[4] = {prow0[2 * s], prow1[2 * s], prow0[2 * s + 1], prow1[2 * s + 1]};
                unsigned bfr[2] = {vbf[2 * s], vbf[2 * s + 1]};
                mma_tf32(o[nt], a, bfr);
            }
        }
        __syncwarp();
    }

    // Epilogue: divide by l, write attn[b, q0+row, h*64 + d]
    float inv0 = 1.f / l0, inv1 = 1.f / l1;
    float* outp = attn + ((size_t)(b * SEQ + q0 + r0)) * DMODEL + h * HDIM;
#pragma unroll
    for (int nt = 0; nt < 8; nt++) {
        int d = nt * 8 + 2 * kq;
        float2 v0 = {o[nt][0] * inv0, o[nt][1] * inv0};
        float2 v1 = {o[nt][2] * inv1, o[nt][3] * inv1};
        *(float2*)(outp + d) = v0;
        *(float2*)(outp + 8 * DMODEL + d) = v1;
    }
}

// ---------------------------------------------------------------------------
extern "C" void kernel_launch(void* const* d_in, const int* in_sizes, int n_in,
                              void* d_out, int out_size)
{
    const float* x     = (const float*)d_in[0];
    const float* qkv_w = (const float*)d_in[1];
    const float* qkv_b = (const float*)d_in[2];
    const float* out_w = (const float*)d_in[3];
    const float* out_b = (const float*)d_in[4];
    float* out = (float*)d_out;

    float *qkv_buf, *attn_buf;
    cudaGetSymbolAddress((void**)&qkv_buf, g_qkv);
    cudaGetSymbolAddress((void**)&attn_buf, g_attn);

    cudaFuncSetAttribute(attn_tc, cudaFuncAttributeMaxDynamicSharedMemorySize,
                         ATTN_SMEM_BYTES);

    {
        dim3 grid(D3 / 128, MROWS / 128);
        gemm_tc<<<grid, 256>>>(x, qkv_w, qkv_b, qkv_buf, MROWS, D3, DMODEL);
    }
    {
        dim3 grid(SEQ / 64, BATCH * NHEAD);
        attn_tc<<<grid, 128, ATTN_SMEM_BYTES>>>(qkv_buf, attn_buf);
    }
    {
        dim3 grid(DMODEL / 128, MROWS / 128);
        gemm_tc<<<grid, 256>>>(attn_buf, out_w, out_b, out, MROWS, DMODEL, DMODEL);
    }
}

// round 4
// speedup vs baseline: 3.4149x; 1.6707x over previous
#include <cuda_runtime.h>
#include <math.h>

#define BATCH 2
#define SEQ   2048
#define DMODEL 1024
#define NHEAD 16
#define HDIM  64
#define D3    3072
#define MROWS (BATCH*SEQ)

// Scratch (no cudaMalloc allowed)
__device__ float g_qkv[(size_t)MROWS * D3];
__device__ float g_attn[(size_t)MROWS * DMODEL];
__device__ float g_xr [(size_t)MROWS * DMODEL];
__device__ float g_w1 [(size_t)D3 * DMODEL];
__device__ float g_w2 [(size_t)DMODEL * DMODEL];

__device__ __forceinline__ unsigned f2tf(float f) {
    unsigned u;
    asm("cvt.rna.tf32.f32 %0, %1;" : "=r"(u) : "f"(f));
    return u;
}
__device__ __forceinline__ float rtf(float f) { return __uint_as_float(f2tf(f)); }

__device__ __forceinline__ void mma_tf32(float* d, const unsigned* a, const unsigned* b) {
    asm volatile(
        "mma.sync.aligned.m16n8k8.row.col.f32.tf32.tf32.f32 "
        "{%0,%1,%2,%3}, {%4,%5,%6,%7}, {%8,%9}, {%0,%1,%2,%3};\n"
        : "+f"(d[0]), "+f"(d[1]), "+f"(d[2]), "+f"(d[3])
        : "r"(a[0]), "r"(a[1]), "r"(a[2]), "r"(a[3]), "r"(b[0]), "r"(b[1]));
}

__device__ __forceinline__ void cp16(float* dst, const float* src) {
    unsigned s = (unsigned)__cvta_generic_to_shared(dst);
    asm volatile("cp.async.cg.shared.global [%0], [%1], 16;\n" :: "r"(s), "l"(src));
}
__device__ __forceinline__ void cpcommit() { asm volatile("cp.async.commit_group;\n"); }
template<int N> __device__ __forceinline__ void cpwait() {
    asm volatile("cp.async.wait_group %0;\n" :: "n"(N));
}

// ---------------------------------------------------------------------------
// Pre-round fp32 -> tf32(RNA) stored as fp32 bits (elementwise, float4)
// ---------------------------------------------------------------------------
__global__ void round_k(const float* __restrict__ in, float* __restrict__ out, int n4)
{
    int i = blockIdx.x * blockDim.x + threadIdx.x;
    if (i < n4) {
        float4 v = ((const float4*)in)[i];
        v.x = rtf(v.x); v.y = rtf(v.y); v.z = rtf(v.z); v.w = rtf(v.w);
        ((float4*)out)[i] = v;
    }
}

// ---------------------------------------------------------------------------
// GEMM NT + bias, tf32 mma, cp.async 3-stage pipeline.
// 128x128 tile, BK=32, 256 threads (8 warps 4x2), warp tile 32x64.
// Smem natural layout, row stride 36 floats (conflict-free scalar frag LDS).
// Inputs pre-rounded to tf32 -> raw-bit fragments, no in-loop cvt.
// ---------------------------------------------------------------------------
#define GS 36
#define GSTAGE (128 * GS)                 // floats per matrix per stage
#define GEMM_SMEM (3 * 2 * GSTAGE * 4)    // 110592 bytes

template<bool ROUND>
__global__ __launch_bounds__(256, 2)
void gemm_tc(const float* __restrict__ A, const float* __restrict__ Bm,
             const float* __restrict__ bias, float* __restrict__ C,
             int M, int N, int K)
{
    extern __shared__ float sm[];
    const int tid = threadIdx.x, warp = tid >> 5, lane = tid & 31;
    const int g = lane >> 2, kq = lane & 3;
    const int wm = warp >> 1, wn = warp & 1;
    const int row0 = blockIdx.y * 128, col0 = blockIdx.x * 128;
    const int nk = K >> 5;
    const int rbase = tid >> 3, cc = (tid & 7) * 4;

    auto issue = [&](int kt) {
        float* as = sm + (kt % 3) * (2 * GSTAGE);
        float* bs = as + GSTAGE;
        const float* Ab = A + (size_t)row0 * K + (size_t)kt * 32;
        const float* Bb = Bm + (size_t)col0 * K + (size_t)kt * 32;
#pragma unroll
        for (int i = 0; i < 4; i++) {
            int r = i * 32 + rbase;
            cp16(as + r * GS + cc, Ab + (size_t)r * K + cc);
            cp16(bs + r * GS + cc, Bb + (size_t)r * K + cc);
        }
        cpcommit();
    };

    issue(0); issue(1);

    float acc[2][8][4];
#pragma unroll
    for (int mt = 0; mt < 2; mt++)
#pragma unroll
        for (int nt = 0; nt < 8; nt++)
#pragma unroll
            for (int i = 0; i < 4; i++) acc[mt][nt][i] = 0.f;

    for (int kt = 0; kt < nk; kt++) {
        if (kt < nk - 1) cpwait<1>(); else cpwait<0>();
        __syncthreads();
        if (kt + 2 < nk) issue(kt + 2);

        const unsigned* au = (const unsigned*)(sm + (kt % 3) * (2 * GSTAGE));
        const unsigned* bu = au + GSTAGE;
#pragma unroll
        for (int s = 0; s < 4; s++) {
            const int kb = s * 8 + kq;
            unsigned af[2][4];
#pragma unroll
            for (int mt = 0; mt < 2; mt++) {
                int r = wm * 32 + mt * 16 + g;
                af[mt][0] = au[r * GS + kb];
                af[mt][1] = au[(r + 8) * GS + kb];
                af[mt][2] = au[r * GS + kb + 4];
                af[mt][3] = au[(r + 8) * GS + kb + 4];
            }
#pragma unroll
            for (int nt = 0; nt < 8; nt++) {
                int c = wn * 64 + nt * 8 + g;
                unsigned bf[2] = { bu[c * GS + kb], bu[c * GS + kb + 4] };
                mma_tf32(acc[0][nt], af[0], bf);
                mma_tf32(acc[1][nt], af[1], bf);
            }
        }
    }

#pragma unroll
    for (int mt = 0; mt < 2; mt++) {
        int r = row0 + wm * 32 + mt * 16 + g;
#pragma unroll
        for (int nt = 0; nt < 8; nt++) {
            int c = col0 + wn * 64 + nt * 8 + 2 * kq;
            float2 bb = *(const float2*)(bias + c);
            float2 v0 = {acc[mt][nt][0] + bb.x, acc[mt][nt][1] + bb.y};
            float2 v1 = {acc[mt][nt][2] + bb.x, acc[mt][nt][3] + bb.y};
            if (ROUND) {
                v0.x = rtf(v0.x); v0.y = rtf(v0.y);
                v1.x = rtf(v1.x); v1.y = rtf(v1.y);
            }
            *(float2*)(C + (size_t)r * N + c) = v0;
            *(float2*)(C + (size_t)(r + 8) * N + c) = v1;
        }
    }
}

// ---------------------------------------------------------------------------
// Flash attention tf32 mma, cp.async double-buffered K/V.
// 128 threads (4 warps), 64 q-rows per block (16 per warp), kv tiles of 64.
// Natural smem layouts, strides: Q/P 68, K 68, V 72 (conflict-free frags).
// P is the only in-loop cvt (RNA). Ps aliases Qs (Q cached in regs).
// ---------------------------------------------------------------------------
#define STQ 68
#define STK 68
#define STV 72
#define QFL (64 * STQ)
#define KFL (64 * STK)
#define VFL (64 * STV)
#define ATTN_SMEM ((QFL + 2 * KFL + 2 * VFL) * 4)   // 89088 bytes

__global__ __launch_bounds__(128, 2)
void attn_tc(const float* __restrict__ qkv, float* __restrict__ attn)
{
    extern __shared__ float sm[];
    float* Qs  = sm;                 // aliased as Ps after Q frags cached
    float* Ks0 = sm + QFL;
    float* Vs0 = Ks0 + 2 * KFL;

    const int tid = threadIdx.x, warp = tid >> 5, lane = tid & 31;
    const int g = lane >> 2, kq = lane & 3;
    const int b = blockIdx.y >> 4, h = blockIdx.y & 15;
    const int q0 = blockIdx.x * 64;
    const float* base = qkv + (size_t)b * SEQ * D3;
    const int rb = tid >> 4, cc = (tid & 15) * 4;

    auto issueKV = [&](int kt) {
        float* kd = Ks0 + (kt & 1) * KFL;
        float* vd = Vs0 + (kt & 1) * VFL;
        const float* kb = base + (size_t)(kt * 64) * D3 + DMODEL + h * HDIM;
        const float* vb = kb + DMODEL;
#pragma unroll
        for (int i = 0; i < 8; i++) {
            int r = i * 8 + rb;
            cp16(kd + r * STK + cc, kb + (size_t)r * D3 + cc);
            cp16(vd + r * STV + cc, vb + (size_t)r * D3 + cc);
        }
        cpcommit();
    };

    issueKV(0);

    // Q load + exact scale (inputs pre-rounded; 0.125 is a power of two)
#pragma unroll
    for (int i = 0; i < 8; i++) {
        int e = i * 128 + tid;
        int r = e >> 4, d = (e & 15) * 4;
        float4 q = *(const float4*)(base + (size_t)(q0 + r) * D3 + h * HDIM + d);
        q.x *= 0.125f; q.y *= 0.125f; q.z *= 0.125f; q.w *= 0.125f;
        *(float4*)(Qs + r * STQ + d) = q;
    }
    __syncthreads();

    const int r0 = warp * 16 + g;
    unsigned qa[2][16];
    {
        const unsigned* Qu = (const unsigned*)Qs;
#pragma unroll
        for (int s = 0; s < 8; s++) {
            qa[0][2*s]   = Qu[r0 * STQ + 8*s + kq];
            qa[0][2*s+1] = Qu[r0 * STQ + 8*s + 4 + kq];
            qa[1][2*s]   = Qu[(r0 + 8) * STQ + 8*s + kq];
            qa[1][2*s+1] = Qu[(r0 + 8) * STQ + 8*s + 4 + kq];
        }
    }

    float m0 = -1e30f, m1 = -1e30f, l0 = 0.f, l1 = 0.f;
    float o[8][4];
#pragma unroll
    for (int nt = 0; nt < 8; nt++)
#pragma unroll
        for (int i = 0; i < 4; i++) o[nt][i] = 0.f;

    unsigned* Pu = (unsigned*)Qs;

    for (int kt = 0; kt < SEQ / 64; kt++) {
        __syncthreads();   // protect buf (kt+1)&1 from iter kt-1 readers
        if (kt + 1 < SEQ / 64) { issueKV(kt + 1); cpwait<1>(); }
        else                   { cpwait<0>(); }
        __syncthreads();

        const unsigned* Ku = (const unsigned*)(Ks0 + (kt & 1) * KFL);
        const unsigned* Vu = (const unsigned*)(Vs0 + (kt & 1) * VFL);

        // S = Q K^T
        float sf[8][4];
#pragma unroll
        for (int nt = 0; nt < 8; nt++)
#pragma unroll
            for (int i = 0; i < 4; i++) sf[nt][i] = 0.f;

#pragma unroll
        for (int s = 0; s < 8; s++) {
            unsigned a[4] = {qa[0][2*s], qa[1][2*s], qa[0][2*s+1], qa[1][2*s+1]};
#pragma unroll
            for (int nt = 0; nt < 8; nt++) {
                int col = nt * 8 + g;
                unsigned bf[2] = { Ku[col * STK + 8*s + kq],
                                   Ku[col * STK + 8*s + 4 + kq] };
                mma_tf32(sf[nt], a, bf);
            }
        }

        // online softmax (rows r0, r0+8); reduce across quad lanes
        float mx0 = -1e30f, mx1 = -1e30f;
#pragma unroll
        for (int nt = 0; nt < 8; nt++) {
            mx0 = fmaxf(mx0, fmaxf(sf[nt][0], sf[nt][1]));
            mx1 = fmaxf(mx1, fmaxf(sf[nt][2], sf[nt][3]));
        }
        mx0 = fmaxf(mx0, __shfl_xor_sync(0xffffffffu, mx0, 1));
        mx0 = fmaxf(mx0, __shfl_xor_sync(0xffffffffu, mx0, 2));
        mx1 = fmaxf(mx1, __shfl_xor_sync(0xffffffffu, mx1, 1));
        mx1 = fmaxf(mx1, __shfl_xor_sync(0xffffffffu, mx1, 2));
        float mn0 = fmaxf(m0, mx0), mn1 = fmaxf(m1, mx1);
        float c0 = __expf(m0 - mn0), c1 = __expf(m1 - mn1);

        float s0 = 0.f, s1 = 0.f;
#pragma unroll
        for (int nt = 0; nt < 8; nt++) {
            int c = nt * 8 + 2 * kq;
            float p0 = __expf(sf[nt][0] - mn0);
            float p1 = __expf(sf[nt][1] - mn0);
            float p2 = __expf(sf[nt][2] - mn1);
            float p3 = __expf(sf[nt][3] - mn1);
            s0 += p0 + p1; s1 += p2 + p3;
            uint2 w0 = {f2tf(p0), f2tf(p1)};
            uint2 w1 = {f2tf(p2), f2tf(p3)};
            *(uint2*)(Pu + r0 * STQ + c) = w0;
            *(uint2*)(Pu + (r0 + 8) * STQ + c) = w1;
        }
        s0 += __shfl_xor_sync(0xffffffffu, s0, 1);
        s0 += __shfl_xor_sync(0xffffffffu, s0, 2);
        s1 += __shfl_xor_sync(0xffffffffu, s1, 1);
        s1 += __shfl_xor_sync(0xffffffffu, s1, 2);
        l0 = l0 * c0 + s0; m0 = mn0;
        l1 = l1 * c1 + s1; m1 = mn1;
#pragma unroll
        for (int nt = 0; nt < 8; nt++) {
            o[nt][0] *= c0; o[nt][1] *= c0;
            o[nt][2] *= c1; o[nt][3] *= c1;
        }
        __syncwarp();   // own-warp rows only: warp-level ordering suffices

        unsigned pa0[16], pa1[16];
#pragma unroll
        for (int s = 0; s < 8; s++) {
            pa0[2*s]   = Pu[r0 * STQ + 8*s + kq];
            pa0[2*s+1] = Pu[r0 * STQ + 8*s + 4 + kq];
            pa1[2*s]   = Pu[(r0 + 8) * STQ + 8*s + kq];
            pa1[2*s+1] = Pu[(r0 + 8) * STQ + 8*s + 4 + kq];
        }

        // O += P V
#pragma unroll
        for (int s = 0; s < 8; s++) {
            unsigned a[4] = {pa0[2*s], pa1[2*s], pa0[2*s+1], pa1[2*s+1]};
#pragma unroll
            for (int nt = 0; nt < 8; nt++) {
                int d = nt * 8 + g;
                unsigned bf[2] = { Vu[(8*s + kq) * STV + d],
                                   Vu[(8*s + 4 + kq) * STV + d] };
                mma_tf32(o[nt], a, bf);
            }
        }
        __syncwarp();
    }

    // epilogue: normalize, round to tf32 for GEMM2, store
    float inv0 = 1.f / l0, inv1 = 1.f / l1;
    float* op = attn + ((size_t)(b * SEQ + q0 + r0)) * DMODEL + h * HDIM;
#pragma unroll
    for (int nt = 0; nt < 8; nt++) {
        int d = nt * 8 + 2 * kq;
        float2 v0 = {rtf(o[nt][0] * inv0), rtf(o[nt][1] * inv0)};
        float2 v1 = {rtf(o[nt][2] * inv1), rtf(o[nt][3] * inv1)};
        *(float2*)(op + d) = v0;
        *(float2*)(op + 8 * DMODEL + d) = v1;
    }
}

// ---------------------------------------------------------------------------
extern "C" void kernel_launch(void* const* d_in, const int* in_sizes, int n_in,
                              void* d_out, int out_size)
{
    const float* x     = (const float*)d_in[0];
    const float* qkv_w = (const float*)d_in[1];
    const float* qkv_b = (const float*)d_in[2];
    const float* out_w = (const float*)d_in[3];
    const float* out_b = (const float*)d_in[4];
    float* out = (float*)d_out;

    float *qkv_buf, *attn_buf, *xr, *w1, *w2;
    cudaGetSymbolAddress((void**)&qkv_buf, g_qkv);
    cudaGetSymbolAddress((void**)&attn_buf, g_attn);
    cudaGetSymbolAddress((void**)&xr, g_xr);
    cudaGetSymbolAddress((void**)&w1, g_w1);
    cudaGetSymbolAddress((void**)&w2, g_w2);

    cudaFuncSetAttribute(gemm_tc<true>,
                         cudaFuncAttributeMaxDynamicSharedMemorySize, GEMM_SMEM);
    cudaFuncSetAttribute(gemm_tc<false>,
                         cudaFuncAttributeMaxDynamicSharedMemorySize, GEMM_SMEM);
    cudaFuncSetAttribute(attn_tc,
                         cudaFuncAttributeMaxDynamicSharedMemorySize, ATTN_SMEM);

    // Pre-round inputs to tf32 (RNA), once
    {
        int n4x = MROWS * DMODEL / 4;
        int n41 = D3 * DMODEL / 4;
        int n42 = DMODEL * DMODEL / 4;
        round_k<<<(n4x + 255) / 256, 256>>>(x, xr, n4x);
        round_k<<<(n41 + 255) / 256, 256>>>(qkv_w, w1, n41);
        round_k<<<(n42 + 255) / 256, 256>>>(out_w, w2, n42);
    }

    {   // QKV projection (emit tf32-rounded outputs for attention)
        dim3 grid(D3 / 128, MROWS / 128);
        gemm_tc<true><<<grid, 256, GEMM_SMEM>>>(xr, w1, qkv_b, qkv_buf,
                                                MROWS, D3, DMODEL);
    }
    {   // fused attention (emits tf32-rounded outputs for GEMM2)
        dim3 grid(SEQ / 64, BATCH * NHEAD);
        attn_tc<<<grid, 128, ATTN_SMEM>>>(qkv_buf, attn_buf);
    }
    {   // output projection (full fp32 epilogue)
        dim3 grid(DMODEL / 128, MROWS / 128);
        gemm_tc<false><<<grid, 256, GEMM_SMEM>>>(attn_buf, w2, out_b, out,
                                                 MROWS, DMODEL, DMODEL);
    }
}